// round 2
// baseline (speedup 1.0000x reference)
#include <cuda_runtime.h>

// Problem constants
#define BATCHSZ   2048
#define MDIM      512      // condensed QP size N*NU
#define NHOR      64
#define ITERS     100
#define STEPSZ    0.01f

// Kernel tiling
#define ROWS      16                    // batch rows per CTA
#define NCTAS     (BATCHSZ / ROWS)      // 128
#define NTHREADS  256
#define UPAD      18                    // padded row stride (floats) for u_s: avoids
                                        // update-phase bank conflicts, keeps 8B align

// --------- f32x2 helpers (FFMA2: full-rate fp32 on B300; 3-reg FFMA is half rate) ---
__device__ __forceinline__ unsigned long long splat2(float b) {
    unsigned long long r;
    asm("mov.b64 %0, {%1, %1};" : "=l"(r) : "f"(b));
    return r;
}
__device__ __forceinline__ void ffma2(unsigned long long& acc,
                                      unsigned long long a,
                                      unsigned long long b) {
    asm("fma.rn.f32x2 %0, %1, %2, %0;" : "+l"(acc) : "l"(a), "l"(b));
}
__device__ __forceinline__ void unpack2(unsigned long long v, float& lo, float& hi) {
    asm("mov.b64 {%0, %1}, %2;" : "=f"(lo), "=f"(hi) : "l"(v));
}

// -----------------------------------------------------------------------------------
// One CTA owns ROWS batch rows and runs all 100 PGD iterations locally.
//   grad[r,m] = sum_k H[m,k] * u[r,k]   (H symmetric -> load H[k,m], coalesced on m)
//   u <- clip(u - step*(grad + f), -1, 1)
// u kept in SMEM, layout u_s[k*UPAD + r] (k-major, rows contiguous -> LDS.64 row pairs,
// broadcast across all threads -> conflict-free).
// f kept in registers (each thread owns exactly its (m, r) entries).
// -----------------------------------------------------------------------------------
__global__ void __launch_bounds__(NTHREADS, 1)
mpc_pgd_kernel(const float* __restrict__ xref,   // [B, NHOR+1, 8]
               const float* __restrict__ H,      // [512, 512]
               const float* __restrict__ Phi,    // [NHOR+1, 8, 8]
               const float* __restrict__ Q,      // [8, 8]
               float* __restrict__ out)          // [B, 512]
{
    __shared__ __align__(16) float u_s[MDIM * UPAD];   // 512*18*4 = 36864 B

    const int t  = threadIdx.x;
    const int b0 = blockIdx.x * ROWS;
    const int m0 = t;            // first owned output column
    const int m1 = t + NTHREADS; // second owned output column (t + 256)

    // ---- init u = 0 ----
    for (int i = t; i < MDIM * UPAD; i += NTHREADS) u_s[i] = 0.0f;

    // ---- compute f for the thread's (m, r) entries into registers ----
    // f[b, kh*8+i] = -2 * sum_l (sum_j Phi[kh,i,j] Q[j,l]) * (xref[b,kh,l]-xref[b,0,l])
    float f_reg[2][ROWS];
    #pragma unroll
    for (int mi = 0; mi < 2; mi++) {
        const int m  = (mi == 0) ? m0 : m1;
        const int kh = m >> 3;
        const int ii = m & 7;
        float PQ[8];
        #pragma unroll
        for (int l = 0; l < 8; l++) {
            float s = 0.0f;
            #pragma unroll
            for (int j = 0; j < 8; j++)
                s += Phi[(kh * 8 + ii) * 8 + j] * Q[j * 8 + l];
            PQ[l] = s;
        }
        for (int r = 0; r < ROWS; r++) {
            const float* xr = xref + (size_t)(b0 + r) * (NHOR + 1) * 8;
            float s = 0.0f;
            #pragma unroll
            for (int l = 0; l < 8; l++)
                s += PQ[l] * (xr[kh * 8 + l] - xr[l]);
            f_reg[mi][r] = -2.0f * s;
        }
    }
    __syncthreads();

    // ---- 100 PGD iterations ----
    for (int it = 0; it < ITERS; it++) {
        // accumulators: 8 row-pairs per column, packed f32x2
        unsigned long long acc0[ROWS / 2], acc1[ROWS / 2];
        #pragma unroll
        for (int p = 0; p < ROWS / 2; p++) { acc0[p] = 0ull; acc1[p] = 0ull; }

        const float* __restrict__ Hc0 = H + m0;
        const float* __restrict__ Hc1 = H + m1;

        #pragma unroll 4
        for (int k = 0; k < MDIM; k++) {
            const float h0 = Hc0[k * MDIM];       // H[k, m0]  (coalesced on t)
            const float h1 = Hc1[k * MDIM];       // H[k, m1]
            const unsigned long long h0p = splat2(h0);
            const unsigned long long h1p = splat2(h1);
            const unsigned long long* up =
                reinterpret_cast<const unsigned long long*>(&u_s[k * UPAD]);
            #pragma unroll
            for (int p = 0; p < ROWS / 2; p++) {
                const unsigned long long u2 = up[p];   // broadcast LDS.64
                ffma2(acc0[p], u2, h0p);
                ffma2(acc1[p], u2, h1p);
            }
        }
        __syncthreads();   // all reads of u done

        // update: u <- clip(u - step*(grad + f))
        #pragma unroll
        for (int p = 0; p < ROWS / 2; p++) {
            float g0lo, g0hi, g1lo, g1hi;
            unpack2(acc0[p], g0lo, g0hi);
            unpack2(acc1[p], g1lo, g1hi);
            const int r0 = 2 * p, r1 = 2 * p + 1;

            float u00 = u_s[m0 * UPAD + r0];
            float u01 = u_s[m0 * UPAD + r1];
            float u10 = u_s[m1 * UPAD + r0];
            float u11 = u_s[m1 * UPAD + r1];

            u00 = fminf(fmaxf(u00 - STEPSZ * (g0lo + f_reg[0][r0]), -1.0f), 1.0f);
            u01 = fminf(fmaxf(u01 - STEPSZ * (g0hi + f_reg[0][r1]), -1.0f), 1.0f);
            u10 = fminf(fmaxf(u10 - STEPSZ * (g1lo + f_reg[1][r0]), -1.0f), 1.0f);
            u11 = fminf(fmaxf(u11 - STEPSZ * (g1hi + f_reg[1][r1]), -1.0f), 1.0f);

            u_s[m0 * UPAD + r0] = u00;
            u_s[m0 * UPAD + r1] = u01;
            u_s[m1 * UPAD + r0] = u10;
            u_s[m1 * UPAD + r1] = u11;
        }
        __syncthreads();   // updates visible before next GEMM
    }

    // ---- write result: out[b, m] ----
    #pragma unroll
    for (int r = 0; r < ROWS; r++) {
        out[(size_t)(b0 + r) * MDIM + m0] = u_s[m0 * UPAD + r];
        out[(size_t)(b0 + r) * MDIM + m1] = u_s[m1 * UPAD + r];
    }
}

extern "C" void kernel_launch(void* const* d_in, const int* in_sizes, int n_in,
                              void* d_out, int out_size) {
    // metadata order: x0, xref, H, Phi, Q   (x0 unused by the reference math)
    const float* xref = (const float*)d_in[1];
    const float* H    = (const float*)d_in[2];
    const float* Phi  = (const float*)d_in[3];
    const float* Q    = (const float*)d_in[4];
    float* out        = (float*)d_out;

    mpc_pgd_kernel<<<NCTAS, NTHREADS>>>(xref, H, Phi, Q, out);
}

// round 7
// speedup vs baseline: 2.0277x; 2.0277x over previous
#include <cuda_runtime.h>
#include <cuda_fp16.h>
#include <cstdint>

#define NGROUP   16
#define NCTAS    128
#define NT       128
#define ITERS    100
#define STEPSZ   0.01f
#define MQ       512
#define XSTRIDE  520          // (64+1)*8 floats per batch row of xref
#define CHUNK_BYTES 16384     // one u chunk: [128 rows][64 f16], swizzled
#define CHUNK_HALFS 8192

// ---- dynamic SMEM map ----
#define SM_BHI   0                       // H slab hi: [64 n][512 k] f16 (swizzled) 64 KB
#define SM_BLO   65536                   // H slab lo                              64 KB
#define SM_STAGE 131072                  // 2 stages x 32 KB (hi 16K + lo 16K)
#define SM_U     (131072 + 65536)        // u master f32 [128][66] = 33792 B
#define SM_TOTAL (SM_U + 128*66*4)       // 230400 B

// ---- device scratch (allocation-free rule: globals only) ----
// Double-buffered u blobs: version v lives in buffer v&1.
__device__ __align__(128) __half g_uhi[2][NCTAS * CHUNK_HALFS];   // 4 MB
__device__ __align__(128) __half g_ulo[2][NCTAS * CHUNK_HALFS];   // 4 MB
// Replay-safe epoch barrier per group (monotonic epoch, count resets per instance)
__device__ unsigned int g_cnt[NGROUP];
__device__ unsigned int g_epoch[NGROUP];

// ---------------- helpers ----------------
__device__ __forceinline__ uint32_t smem_u32(const void* p) {
    uint32_t a;
    asm("{ .reg .u64 t; cvta.to.shared.u64 t, %1; cvt.u32.u64 %0, t; }" : "=r"(a) : "l"(p));
    return a;
}
__device__ __forceinline__ void ldsm4(uint32_t* r, uint32_t addr) {
    asm volatile("ldmatrix.sync.aligned.m8n8.x4.shared.b16 {%0,%1,%2,%3}, [%4];"
                 : "=r"(r[0]), "=r"(r[1]), "=r"(r[2]), "=r"(r[3]) : "r"(addr));
}
__device__ __forceinline__ void mma_f16(float* c, const uint32_t* a, uint32_t b0, uint32_t b1) {
    asm volatile("mma.sync.aligned.m16n8k16.row.col.f32.f16.f16.f32 "
                 "{%0,%1,%2,%3}, {%4,%5,%6,%7}, {%8,%9}, {%0,%1,%2,%3};"
                 : "+f"(c[0]), "+f"(c[1]), "+f"(c[2]), "+f"(c[3])
                 : "r"(a[0]), "r"(a[1]), "r"(a[2]), "r"(a[3]), "r"(b0), "r"(b1));
}
__device__ __forceinline__ void cpasync16(uint32_t daddr, const void* saddr) {
    asm volatile("cp.async.cg.shared.global [%0], [%1], 16;"
                 :: "r"(daddr), "l"(saddr) : "memory");
}
__device__ __forceinline__ uint32_t packh2(__half a, __half b) {
    __half_raw ar = a, br = b;
    uint32_t r;
    asm("mov.b32 %0, {%1, %2};" : "=r"(r) : "h"((unsigned short)ar.x), "h"((unsigned short)br.x));
    return r;
}

// ---- epoch barrier (8 arrivals per instance; replay-safe) ----
__device__ __forceinline__ void gbar_arrive(int group) {
    __threadfence();
    unsigned int old = atomicAdd(&g_cnt[group], 1u);
    if (old == 7u) {
        *(volatile unsigned int*)&g_cnt[group] = 0u;
        __threadfence();
        atomicAdd(&g_epoch[group], 1u);
    }
}
__device__ __forceinline__ void gbar_wait(int group, unsigned int epoch0, int target) {
    const volatile unsigned int* ep = &g_epoch[group];
    while ((int)(*ep - epoch0) < target) {}
    __threadfence();
}

// -----------------------------------------------------------------------------------
// CTA = (group, colcta): owns batch rows [group*128, +128) x output cols
// [colcta*64, +64). H slab (64 n x 512 k) as split f16 hi/lo resident in SMEM.
// grad block = u[128x512] @ Hslab^T via mma.sync m16n8k16 (3-term split-f16).
// u exchanged per iteration through gmem blobs: blob c = u[128 rows][64 k of CTA c],
// swizzled [row*128 + ((k/8 ^ row&7)*16) + (k%8)*2] so ldmatrix is conflict-free.
// -----------------------------------------------------------------------------------
__global__ void __launch_bounds__(NT, 1)
mpc_hmma_kernel(const float* __restrict__ xref, const float* __restrict__ H,
                const float* __restrict__ Phi, const float* __restrict__ Q,
                float* __restrict__ out)
{
    extern __shared__ char smem[];
    const uint32_t sbase = smem_u32(smem);
    const int tid  = threadIdx.x;
    const int lane = tid & 31, w = tid >> 5;
    const int group = blockIdx.x >> 3, colcta = blockIdx.x & 7;
    const int myblob = blockIdx.x;

    // capture epoch BEFORE our own instance-0 arrival (peers can't bump the
    // epoch until all 8 CTAs arrive, so this read is race-free)
    unsigned int epoch0 = 0;
    if (tid == 0) epoch0 = *(volatile unsigned int*)&g_epoch[group];

    // ---- zero u master ----
    for (int i = tid; i < 128 * 66; i += NT) ((float*)(smem + SM_U))[i] = 0.0f;

    // ---- build H slab hi/lo (swizzled) ----
    for (int idx = tid; idx < 64 * 512; idx += NT) {
        const int n = idx >> 9, k = idx & 511;
        const float h = H[(size_t)(colcta * 64 + n) * MQ + k];
        const __half hh = __float2half_rn(h);
        const __half hl = __float2half_rn(h - __half2float(hh));
        const uint32_t off = (uint32_t)n * 1024u + ((((uint32_t)(k >> 3)) ^ (uint32_t)(n & 7)) << 4)
                           + (uint32_t)(k & 7) * 2u;
        *(__half*)(smem + SM_BHI + off) = hh;
        *(__half*)(smem + SM_BLO + off) = hl;
    }
    // ---- PQ staged temporarily in the stage area ----
    float* PQs = (float*)(smem + SM_STAGE);
    for (int idx = tid; idx < 512; idx += NT) {
        const int khl = idx >> 6, ii = (idx >> 3) & 7, l = idx & 7;
        const int kh = colcta * 8 + khl;
        float s = 0.0f;
        #pragma unroll
        for (int j = 0; j < 8; j++) s += Phi[(kh * 8 + ii) * 8 + j] * Q[j * 8 + l];
        PQs[idx] = s;
    }
    // ---- zero own blob v0 (u0 = 0) ----
    {
        uint4 z = make_uint4(0, 0, 0, 0);
        uint4* bh = (uint4*)((char*)g_uhi[0] + (size_t)myblob * CHUNK_BYTES);
        uint4* bl = (uint4*)((char*)g_ulo[0] + (size_t)myblob * CHUNK_BYTES);
        for (int i = tid; i < CHUNK_BYTES / 16; i += NT) { bh[i] = z; bl[i] = z; }
    }
    __syncthreads();

    // ---- f in registers: thread owns rows rA+{0,8,16,24}, cols 8nt+cB+{0,1} ----
    const int rA = 32 * w + (lane >> 2);
    const int cB = 2 * (lane & 3);
    float f_reg[2][8][4];
    #pragma unroll
    for (int rr = 0; rr < 4; rr++) {
        const int tm = rr >> 1, pair = rr & 1;
        const int row = rA + tm * 16 + pair * 8;
        const float* xr = xref + (size_t)(group * 128 + row) * XSTRIDE;
        float x0l[8];
        #pragma unroll
        for (int l = 0; l < 8; l++) x0l[l] = xr[l];
        float dxr[8][8];
        #pragma unroll
        for (int khl = 0; khl < 8; khl++) {
            const int kh = colcta * 8 + khl;
            #pragma unroll
            for (int l = 0; l < 8; l++) dxr[khl][l] = xr[kh * 8 + l] - x0l[l];
        }
        #pragma unroll
        for (int nt = 0; nt < 8; nt++)
            #pragma unroll
            for (int e = 0; e < 2; e++) {
                const int ii = cB + e;
                float s = 0.0f;
                #pragma unroll
                for (int l = 0; l < 8; l++) s += PQs[nt * 64 + ii * 8 + l] * dxr[nt][l];
                f_reg[tm][nt][pair * 2 + e] = -2.0f * s;
            }
    }
    __threadfence();     // own blob-zero stores visible before publish
    __syncthreads();     // PQ reads done before stages get overwritten
    if (tid == 0) gbar_arrive(group);   // instance 0: blob v0 published

    // ---- ldmatrix address precomputation ----
    const int rowA0 = 32 * w + (lane & 15);             // A tile row (this warp)
    const uint32_t aOff0 = (uint32_t)rowA0 * 128u;
    const int mx = rowA0 & 7;
    const int kparA = lane >> 4;                        // 0: k+0, 1: k+8
    const int nrow0 = (lane & 7) + ((lane >> 4) << 3);  // B tile n-row
    const int nx = nrow0 & 7;
    const int kparB = (lane >> 3) & 1;
    const uint32_t bBase = sbase + SM_BHI + (uint32_t)nrow0 * 1024u;

    // ================== main PGD loop ==================
    for (int it = 0; it < ITERS; it++) {
        float acc[2][8][4];
        #pragma unroll
        for (int tm = 0; tm < 2; tm++)
            #pragma unroll
            for (int nt = 0; nt < 8; nt++)
                #pragma unroll
                for (int j = 0; j < 4; j++) acc[tm][nt][j] = 0.0f;

        if (tid == 0) gbar_wait(group, epoch0, it + 1);   // all blobs v_it ready
        __syncthreads();

        const char* srcHi = (const char*)g_uhi[it & 1] + (size_t)group * 8 * CHUNK_BYTES;
        const char* srcLo = (const char*)g_ulo[it & 1] + (size_t)group * 8 * CHUNK_BYTES;

        // issue chunks 0 and 1 (2-stage cp.async pipeline)
        #pragma unroll
        for (int c0 = 0; c0 < 2; c0++) {
            const uint32_t dst = sbase + SM_STAGE + (uint32_t)(c0 & 1) * 32768u;
            const char* sH = srcHi + (size_t)c0 * CHUNK_BYTES;
            const char* sL = srcLo + (size_t)c0 * CHUNK_BYTES;
            #pragma unroll
            for (int j = 0; j < 8; j++) {
                const uint32_t off = (uint32_t)(tid + j * 128) * 16u;
                cpasync16(dst + off, sH + off);
                cpasync16(dst + 16384u + off, sL + off);
            }
            asm volatile("cp.async.commit_group;" ::: "memory");
        }

        for (int c = 0; c < 8; c++) {
            if (c < 7) asm volatile("cp.async.wait_group 1;" ::: "memory");
            else       asm volatile("cp.async.wait_group 0;" ::: "memory");
            __syncthreads();   // chunk c landed for ALL threads

            const uint32_t stA = sbase + SM_STAGE + (uint32_t)(c & 1) * 32768u;
            #pragma unroll
            for (int ks = 0; ks < 4; ks++) {
                uint32_t ah[2][4], al[2][4];
                const uint32_t unitA = (uint32_t)(ks * 2 + kparA);
                const uint32_t sa = ((unitA ^ (uint32_t)mx) << 4);
                #pragma unroll
                for (int tm = 0; tm < 2; tm++) {
                    ldsm4(ah[tm], stA + aOff0 + (uint32_t)tm * 2048u + sa);
                    ldsm4(al[tm], stA + 16384u + aOff0 + (uint32_t)tm * 2048u + sa);
                }
                uint32_t bh[4][4], bl[4][4];
                const uint32_t unitB = (uint32_t)(c * 8 + ks * 2 + kparB);
                const uint32_t sb = ((unitB ^ (uint32_t)nx) << 4);
                #pragma unroll
                for (int g = 0; g < 4; g++) {
                    ldsm4(bh[g], bBase + (uint32_t)g * 16384u + sb);
                    ldsm4(bl[g], bBase + 65536u + (uint32_t)g * 16384u + sb);
                }
                // term 1: u_hi * H_hi
                #pragma unroll
                for (int tm = 0; tm < 2; tm++)
                    #pragma unroll
                    for (int nt = 0; nt < 8; nt++)
                        mma_f16(acc[tm][nt], ah[tm], bh[nt >> 1][(nt & 1) * 2], bh[nt >> 1][(nt & 1) * 2 + 1]);
                // term 2: u_lo * H_hi
                #pragma unroll
                for (int tm = 0; tm < 2; tm++)
                    #pragma unroll
                    for (int nt = 0; nt < 8; nt++)
                        mma_f16(acc[tm][nt], al[tm], bh[nt >> 1][(nt & 1) * 2], bh[nt >> 1][(nt & 1) * 2 + 1]);
                // term 3: u_hi * H_lo
                #pragma unroll
                for (int tm = 0; tm < 2; tm++)
                    #pragma unroll
                    for (int nt = 0; nt < 8; nt++)
                        mma_f16(acc[tm][nt], ah[tm], bl[nt >> 1][(nt & 1) * 2], bl[nt >> 1][(nt & 1) * 2 + 1]);
            }
            __syncthreads();   // all threads done reading stage (c&1)
            if (c < 6) {       // refill this stage with chunk c+2
                const uint32_t dst = sbase + SM_STAGE + (uint32_t)(c & 1) * 32768u;
                const char* sH = srcHi + (size_t)(c + 2) * CHUNK_BYTES;
                const char* sL = srcLo + (size_t)(c + 2) * CHUNK_BYTES;
                #pragma unroll
                for (int j = 0; j < 8; j++) {
                    const uint32_t off = (uint32_t)(tid + j * 128) * 16u;
                    cpasync16(dst + off, sH + off);
                    cpasync16(dst + 16384u + off, sL + off);
                }
                asm volatile("cp.async.commit_group;" ::: "memory");
            }
        }

        // ---- epilogue: u <- clip(u - step*(grad + f)); publish / write out ----
        const bool lastIt = (it == ITERS - 1);
        char* dHi = (char*)g_uhi[(it + 1) & 1] + (size_t)myblob * CHUNK_BYTES;
        char* dLo = (char*)g_ulo[(it + 1) & 1] + (size_t)myblob * CHUNK_BYTES;
        #pragma unroll
        for (int tm = 0; tm < 2; tm++)
            #pragma unroll
            for (int nt = 0; nt < 8; nt++)
                #pragma unroll
                for (int pair = 0; pair < 2; pair++) {
                    const int row  = rA + tm * 16 + pair * 8;
                    const int col0 = 8 * nt + cB;
                    float* up = (float*)(smem + SM_U) + row * 66 + col0;
                    float v0 = up[0] - STEPSZ * (acc[tm][nt][pair * 2 + 0] + f_reg[tm][nt][pair * 2 + 0]);
                    float v1 = up[1] - STEPSZ * (acc[tm][nt][pair * 2 + 1] + f_reg[tm][nt][pair * 2 + 1]);
                    v0 = fminf(fmaxf(v0, -1.0f), 1.0f);
                    v1 = fminf(fmaxf(v1, -1.0f), 1.0f);
                    up[0] = v0; up[1] = v1;
                    if (!lastIt) {
                        const __half h0 = __float2half_rn(v0), h1 = __float2half_rn(v1);
                        const __half l0 = __float2half_rn(v0 - __half2float(h0));
                        const __half l1 = __float2half_rn(v1 - __half2float(h1));
                        const uint32_t off = (uint32_t)row * 128u
                                           + (((uint32_t)nt ^ (uint32_t)(row & 7)) << 4)
                                           + (uint32_t)cB * 2u;
                        *(uint32_t*)(dHi + off) = packh2(h0, h1);
                        *(uint32_t*)(dLo + off) = packh2(l0, l1);
                    } else {
                        float2 v; v.x = v0; v.y = v1;
                        *(float2*)(out + (size_t)(group * 128 + row) * MQ + colcta * 64 + col0) = v;
                    }
                }
        if (!lastIt) {
            __threadfence();
            __syncthreads();
            if (tid == 0) gbar_arrive(group);   // instance it+1: blob v_{it+1} published
        }
    }
}

extern "C" void kernel_launch(void* const* d_in, const int* in_sizes, int n_in,
                              void* d_out, int out_size) {
    // metadata order: x0, xref, H, Phi, Q  (x0 unused by the reference math)
    const float* xref = (const float*)d_in[1];
    const float* H    = (const float*)d_in[2];
    const float* Phi  = (const float*)d_in[3];
    const float* Q    = (const float*)d_in[4];
    float* out        = (float*)d_out;

    cudaFuncSetAttribute(mpc_hmma_kernel, cudaFuncAttributeMaxDynamicSharedMemorySize, SM_TOTAL);
    mpc_hmma_kernel<<<NCTAS, NT, SM_TOTAL>>>(xref, H, Phi, Q, out);
}